// round 14
// baseline (speedup 1.0000x reference)
#include <cuda_runtime.h>
#include <cuda_fp16.h>
#include <math.h>
#include <stdint.h>

#define B_TOT 2048   // 64 * 32 rows
#define S_DIM 2048
#define N_AG  32
#define EMB   64
#define NP    2304   // padded concatenated output cols (2240 -> 18*128)

// Scratch (device globals: no allocation allowed in kernel_launch)
__device__ __half g_Wh[S_DIM * NP];    // Wcat fp16 [K][N]
__device__ __half g_Sh[B_TOT * S_DIM]; // st fp16
__device__ float g_bcat[NP];
__device__ float g_Y[B_TOT * NP];      // fp16-mma st @ Wcat + bcat (fp32 accum)
__device__ float g_q1[B_TOT * N_AG];   // masked-mix outputs

// ---------------------------------------------------------------------------
// helpers
// ---------------------------------------------------------------------------
__device__ __forceinline__ void ldsm_x4(uint32_t* r, const void* p) {
    uint32_t a = (uint32_t)__cvta_generic_to_shared(p);
    asm volatile("ldmatrix.sync.aligned.m8n8.x4.shared.b16 {%0,%1,%2,%3}, [%4];"
                 : "=r"(r[0]), "=r"(r[1]), "=r"(r[2]), "=r"(r[3]) : "r"(a));
}
__device__ __forceinline__ void ldsm_x4t(uint32_t* r, const void* p) {
    uint32_t a = (uint32_t)__cvta_generic_to_shared(p);
    asm volatile("ldmatrix.sync.aligned.m8n8.x4.trans.shared.b16 {%0,%1,%2,%3}, [%4];"
                 : "=r"(r[0]), "=r"(r[1]), "=r"(r[2]), "=r"(r[3]) : "r"(a));
}
__device__ __forceinline__ void ldsm_x2t(uint32_t* r, const void* p) {
    uint32_t a = (uint32_t)__cvta_generic_to_shared(p);
    asm volatile("ldmatrix.sync.aligned.m8n8.x2.trans.shared.b16 {%0,%1}, [%2];"
                 : "=r"(r[0]), "=r"(r[1]) : "r"(a));
}
__device__ __forceinline__ void mma_fp16(float* d, const uint32_t* a, const uint32_t* b) {
    asm volatile(
        "mma.sync.aligned.m16n8k16.row.col.f32.f16.f16.f32 "
        "{%0,%1,%2,%3},{%4,%5,%6,%7},{%8,%9},{%0,%1,%2,%3};"
        : "+f"(d[0]), "+f"(d[1]), "+f"(d[2]), "+f"(d[3])
        : "r"(a[0]), "r"(a[1]), "r"(a[2]), "r"(a[3]), "r"(b[0]), "r"(b[1]));
}
__device__ __forceinline__ void cp16(uint32_t dst, const void* src) {
    asm volatile("cp.async.cg.shared.global [%0], [%1], 16;" :: "r"(dst), "l"(src));
}
#define CP_COMMIT()  asm volatile("cp.async.commit_group;" ::: "memory")
#define CP_WAIT(n)   asm volatile("cp.async.wait_group %0;" :: "n"(n) : "memory")

// ---------------------------------------------------------------------------
// Pack (vectorized): concat weights -> fp16, st -> fp16, bias.
// ---------------------------------------------------------------------------
__global__ void pack_kernel(const float* __restrict__ st,
                            const float* __restrict__ Ww1, const float* __restrict__ bw1,
                            const float* __restrict__ Wwf, const float* __restrict__ bwf,
                            const float* __restrict__ Wb1, const float* __restrict__ bb1,
                            const float* __restrict__ Wv1, const float* __restrict__ bv1) {
    const int idx = blockIdx.x * blockDim.x + threadIdx.x;
    const int stride = gridDim.x * blockDim.x;

    if (idx < NP) {
        int n = idx;
        float bv;
        if (n < 2048)      bv = bw1[n];
        else if (n < 2112) bv = bwf[n - 2048];
        else if (n < 2176) bv = bb1[n - 2112];
        else if (n < 2240) bv = bv1[n - 2176];
        else               bv = 0.f;
        g_bcat[n] = bv;
    }

    const int WQ = S_DIM * (NP / 4);
    for (int i = idx; i < WQ; i += stride) {
        int k = i / 576;
        int n = (i - k * 576) * 4;
        float4 v;
        if (n < 2048)      v = *(const float4*)(Ww1 + (size_t)k * 2048 + n);
        else if (n < 2112) v = *(const float4*)(Wwf + (size_t)k * 64 + (n - 2048));
        else if (n < 2176) v = *(const float4*)(Wb1 + (size_t)k * 64 + (n - 2112));
        else if (n < 2240) v = *(const float4*)(Wv1 + (size_t)k * 64 + (n - 2176));
        else               v = make_float4(0.f, 0.f, 0.f, 0.f);
        __half2* ph = (__half2*)(g_Wh + (size_t)i * 4);
        ph[0] = __floats2half2_rn(v.x, v.y);
        ph[1] = __floats2half2_rn(v.z, v.w);
    }

    const int SQ = B_TOT * (S_DIM / 4);
    for (int i = idx; i < SQ; i += stride) {
        float4 v = *(const float4*)(st + (size_t)i * 4);
        __half2* ph = (__half2*)(g_Sh + (size_t)i * 4);
        ph[0] = __floats2half2_rn(v.x, v.y);
        ph[1] = __floats2half2_rn(v.z, v.w);
    }
}

// ---------------------------------------------------------------------------
// K1: Y = fp16(st) @ fp16(Wcat) + bcat, single fp16 MMA, fp32 accum.
// Block 128x128, 8 warps (4m x 2n), K-chunk 64, cp.async double buffer.
// ---------------------------------------------------------------------------
#define K1_OFF_A  0
#define K1_OFF_B  18432
#define K1_BUF    35840
#define K1_SMEM   (2 * K1_BUF)

__global__ __launch_bounds__(256, 1) void gemm_f16() {
    extern __shared__ char smem[];
    const uint32_t sbase = (uint32_t)__cvta_generic_to_shared(smem);

    const int bn = blockIdx.x * 128;
    const int bm = blockIdx.y * 128;
    const int tid = threadIdx.x;
    const int lane = tid & 31;
    const int warp = tid >> 5;
    const int wm = warp & 3;
    const int wn = warp >> 2;

    const int ra  = tid >> 3,  ca = tid & 7;
    const int rb  = tid >> 4,  cb = tid & 15;

    auto issue = [&](int c, int bufi) {
        const int k0 = c * 64;
        const uint32_t bb = sbase + bufi * K1_BUF;
#pragma unroll
        for (int l = 0; l < 4; l++) {
            int r = ra + l * 32;
            cp16(bb + K1_OFF_A + (uint32_t)r * 144 + ca * 16,
                 g_Sh + (size_t)(bm + r) * S_DIM + k0 + ca * 8);
            int rr = rb + l * 16;
            cp16(bb + K1_OFF_B + (uint32_t)rr * 272 + cb * 16,
                 g_Wh + (size_t)(k0 + rr) * NP + bn + cb * 8);
        }
    };

    float d1[2][8][4];
#pragma unroll
    for (int i = 0; i < 2; i++)
#pragma unroll
        for (int j = 0; j < 8; j++)
#pragma unroll
            for (int c = 0; c < 4; c++) d1[i][j][c] = 0.f;

    issue(0, 0);
    CP_COMMIT();

    for (int c = 0; c < 32; c++) {
        const int bufi = c & 1;
        char* base = smem + bufi * K1_BUF;
        __half* Ah = (__half*)(base + K1_OFF_A);
        __half* Bh = (__half*)(base + K1_OFF_B);

        if (c < 31) {
            issue(c + 1, bufi ^ 1);
            CP_COMMIT();
            CP_WAIT(1);
        } else {
            CP_WAIT(0);
        }
        __syncthreads();

#pragma unroll
        for (int ks = 0; ks < 4; ks++) {
            uint32_t ah[2][4];
#pragma unroll
            for (int mf = 0; mf < 2; mf++) {
                const int ro = (wm * 32 + mf * 16 + (lane & 15)) * 72 + ks * 16 + (lane >> 4) * 8;
                ldsm_x4(ah[mf], &Ah[ro]);
            }
            uint32_t bh[8][2];
#pragma unroll
            for (int nq = 0; nq < 4; nq++) {
                const int bo = (ks * 16 + (lane & 15)) * 136 + wn * 64 + nq * 16 + (lane >> 4) * 8;
                uint32_t t[4];
                ldsm_x4t(t, &Bh[bo]);
                bh[nq * 2][0] = t[0]; bh[nq * 2][1] = t[1];
                bh[nq * 2 + 1][0] = t[2]; bh[nq * 2 + 1][1] = t[3];
            }
#pragma unroll
            for (int mf = 0; mf < 2; mf++)
#pragma unroll
                for (int nf = 0; nf < 8; nf++)
                    mma_fp16(d1[mf][nf], ah[mf], bh[nf]);
        }
        __syncthreads();
    }

    // epilogue: Y = d1 + bias
#pragma unroll
    for (int mf = 0; mf < 2; mf++) {
        int r0 = bm + wm * 32 + mf * 16 + (lane >> 2);
#pragma unroll
        for (int nf = 0; nf < 8; nf++) {
            int c = bn + wn * 64 + nf * 8 + (lane & 3) * 2;
            float2 bc = *(const float2*)&g_bcat[c];
            float2 o0 = { d1[mf][nf][0] + bc.x, d1[mf][nf][1] + bc.y };
            float2 o1 = { d1[mf][nf][2] + bc.x, d1[mf][nf][3] + bc.y };
            *(float2*)(g_Y + (size_t)r0 * NP + c) = o0;
            *(float2*)(g_Y + (size_t)(r0 + 8) * NP + c) = o1;
        }
    }
}

// ---------------------------------------------------------------------------
// K2 v3 (persistent, 32-row items, paired group staging):
//   item = (32-row tile, agent): 2048 items -> 6.92/CTA, max 7 (1.2% tail).
//   8 warps as 1m x 8n: each warp covers all 32 rows (2 m-frags) x 8 cols.
//   A fragments hoisted once per item; B via ldmatrix.x2.trans.
//   w1 groups staged in PAIRS (one sync per 2 groups): 18 syncs/item.
// ---------------------------------------------------------------------------
#define K2_GRID    296
#define K2_ITEMS   2048
#define K2_OFF_W   4608
#define K2_PAIRB   18432           // bytes per pair buffer (2 groups x 64x72 fp16)
#define K2_GRPB    9216            // bytes per group slot
#define K2_OFF_QS  41472
#define K2_OFF_RED 45696
#define K2_SMEM    46720
__global__ __launch_bounds__(256, 2) void corr_mma(const float* __restrict__ qs,
                                                   const float* __restrict__ Wv2,
                                                   const float* __restrict__ bv2) {
    extern __shared__ char smem[];
    const uint32_t sbase = (uint32_t)__cvta_generic_to_shared(smem);
    __half* Sf  = (__half*)smem;                    // [32][72]
    __half* Wgf = (__half*)(smem + K2_OFF_W);       // [2 pairs][2 groups][64][72]
    float* qs_s = (float*)(smem + K2_OFF_QS);       // [32][33]
    float* red  = (float*)(smem + K2_OFF_RED);      // [32][8]

    const int tid = threadIdx.x;
    const int lane = tid & 31;
    const int warp = tid >> 5;          // 0..7 -> 8 cols each
    const int wr = tid >> 3, wc8 = tid & 7;
    const int rq = lane >> 2;           // row-in-frag 0..7
    const int cq = (lane & 3) * 2;      // col pair within warp's 8
    const float bv2v = bv2[0];

    for (int item = blockIdx.x; item < K2_ITEMS; item += K2_GRID) {
        const int bt0 = (item & 63) * 32;
        const int ag  = item >> 6;

        __syncthreads();   // previous item fully done before restaging

        // stage st chunk (32 x 64 fp16): 256 uint4, 1/thread
        {
            int r = tid >> 3, c8 = tid & 7;
            *(uint4*)&Sf[r * 72 + c8 * 8] =
                *(const uint4*)(g_Sh + (size_t)(bt0 + r) * S_DIM + ag * 64 + c8 * 8);
        }
        // stage qs tile (32 x 32): 4/thread
#pragma unroll
        for (int l = 0; l < 4; l++) {
            int idx = l * 256 + tid;
            int r = idx >> 5, c = idx & 31;
            qs_s[r * 33 + c] = qs[(size_t)(bt0 + r) * N_AG + c];
        }

        auto issueG = [&](int g, int pair, int slot) {
#pragma unroll
            for (int l = 0; l < 2; l++) {
                int r = wr + l * 32;
                cp16(sbase + K2_OFF_W + pair * K2_PAIRB + slot * K2_GRPB
                         + (uint32_t)r * 144 + wc8 * 16,
                     g_Wh + (size_t)(ag * 64 + r) * NP + g * 64 + wc8 * 8);
            }
        };

        issueG(0, 0, 0);
        issueG(1, 0, 1);
        CP_COMMIT();
        __syncthreads();   // Sf staged

        // hoist A fragments (invariant across groups): 2 m-frags x 4 ks
        uint32_t ah[2][4][4];
#pragma unroll
        for (int mf = 0; mf < 2; mf++)
#pragma unroll
            for (int ks = 0; ks < 4; ks++) {
                const int ro = (mf * 16 + (lane & 15)) * 72 + ks * 16 + (lane >> 4) * 8;
                ldsm_x4(ah[mf][ks], &Sf[ro]);
            }

        // correction MMA for one group (this warp's 8 cols): c[mf][4]
        auto computeC = [&](const __half* Wg, float (&c)[2][4]) {
#pragma unroll
            for (int mf = 0; mf < 2; mf++)
#pragma unroll
                for (int q = 0; q < 4; q++) c[mf][q] = 0.f;
#pragma unroll
            for (int ks = 0; ks < 4; ks++) {
                uint32_t t[2];
                ldsm_x2t(t, &Wg[(ks * 16 + (lane & 15)) * 72 + warp * 8]);
                mma_fp16(c[0], ah[0][ks], t);
                mma_fp16(c[1], ah[1][ks], t);
            }
        };

        // h[slot][2]: slot = mf*2 + rh; row = mf*16 + rq + rh*8; cols warp*8+cq..+1
        float h[4][2];
#pragma unroll
        for (int s = 0; s < 4; s++) { h[s][0] = 0.f; h[s][1] = 0.f; }
        float vp[4] = {0.f, 0.f, 0.f, 0.f};

        // ---- hot loop: 16 pairs cover w1 groups 0..31 ----
        for (int p = 0; p < 16; p++) {
            CP_WAIT(0);
            __syncthreads();
            if (p < 15) {
                issueG(2 * p + 2, (p + 1) & 1, 0);
                issueG(2 * p + 3, (p + 1) & 1, 1);
            } else {
                issueG(33, (p + 1) & 1, 0);
                issueG(34, (p + 1) & 1, 1);
            }
            CP_COMMIT();

#pragma unroll
            for (int sl = 0; sl < 2; sl++) {
                const int g = 2 * p + sl;
                // Y + qs loads first; MMAs hide latency
                float2 yv[4];
                float qv[4];
#pragma unroll
                for (int s = 0; s < 4; s++) {
                    int rl = (s >> 1) * 16 + rq + (s & 1) * 8;
                    yv[s] = *(const float2*)(g_Y + (size_t)(bt0 + rl) * NP
                                             + g * 64 + warp * 8 + cq);
                    qv[s] = qs_s[rl * 33 + g];
                }
                float c[2][4];
                computeC(Wgf + ((p & 1) * K2_PAIRB + sl * K2_GRPB) / 2, c);
#pragma unroll
                for (int mf = 0; mf < 2; mf++) {
                    int s0 = mf * 2, s1 = mf * 2 + 1;
                    h[s0][0] = fmaf(qv[s0], fabsf(yv[s0].x - c[mf][0]), h[s0][0]);
                    h[s0][1] = fmaf(qv[s0], fabsf(yv[s0].y - c[mf][1]), h[s0][1]);
                    h[s1][0] = fmaf(qv[s1], fabsf(yv[s1].x - c[mf][2]), h[s1][0]);
                    h[s1][1] = fmaf(qv[s1], fabsf(yv[s1].y - c[mf][3]), h[s1][1]);
                }
            }
        }

        // ---- tail pair (33: b1/elu, 34: v1) in pair buffer 0 ----
        CP_WAIT(0);
        __syncthreads();
        issueG(32, 1, 0);
        CP_COMMIT();
        {
            // group 33: hidden = elu(h + m)
            float2 yv[4];
#pragma unroll
            for (int s = 0; s < 4; s++) {
                int rl = (s >> 1) * 16 + rq + (s & 1) * 8;
                yv[s] = *(const float2*)(g_Y + (size_t)(bt0 + rl) * NP
                                         + 33 * 64 + warp * 8 + cq);
            }
            float c[2][4];
            computeC(Wgf + 0, c);
#pragma unroll
            for (int mf = 0; mf < 2; mf++) {
                int s0 = mf * 2, s1 = mf * 2 + 1;
                float t;
                t = h[s0][0] + (yv[s0].x - c[mf][0]); h[s0][0] = t > 0.f ? t : expm1f(t);
                t = h[s0][1] + (yv[s0].y - c[mf][1]); h[s0][1] = t > 0.f ? t : expm1f(t);
                t = h[s1][0] + (yv[s1].x - c[mf][2]); h[s1][0] = t > 0.f ? t : expm1f(t);
                t = h[s1][1] + (yv[s1].y - c[mf][3]); h[s1][1] = t > 0.f ? t : expm1f(t);
            }
        }
        {
            // group 34: vp += relu(m) * Wv2
            float2 yv[4];
#pragma unroll
            for (int s = 0; s < 4; s++) {
                int rl = (s >> 1) * 16 + rq + (s & 1) * 8;
                yv[s] = *(const float2*)(g_Y + (size_t)(bt0 + rl) * NP
                                         + 34 * 64 + warp * 8 + cq);
            }
            int e = warp * 8 + cq;
            float w0 = Wv2[e], w1 = Wv2[e + 1];
            float c[2][4];
            computeC(Wgf + K2_GRPB / 2, c);
#pragma unroll
            for (int mf = 0; mf < 2; mf++) {
                int s0 = mf * 2, s1 = mf * 2 + 1;
                vp[s0] = fmaf(fmaxf(yv[s0].x - c[mf][0], 0.f), w0, vp[s0]);
                vp[s0] = fmaf(fmaxf(yv[s0].y - c[mf][1], 0.f), w1, vp[s0]);
                vp[s1] = fmaf(fmaxf(yv[s1].x - c[mf][2], 0.f), w0, vp[s1]);
                vp[s1] = fmaf(fmaxf(yv[s1].y - c[mf][3], 0.f), w1, vp[s1]);
            }
        }

        // ---- group 32 (w_final) in pair buffer 1 slot 0 ----
        CP_WAIT(0);
        __syncthreads();
        float sacc[4] = { vp[0], vp[1], vp[2], vp[3] };
        {
            float2 yv[4];
#pragma unroll
            for (int s = 0; s < 4; s++) {
                int rl = (s >> 1) * 16 + rq + (s & 1) * 8;
                yv[s] = *(const float2*)(g_Y + (size_t)(bt0 + rl) * NP
                                         + 32 * 64 + warp * 8 + cq);
            }
            float c[2][4];
            computeC(Wgf + K2_PAIRB / 2, c);
#pragma unroll
            for (int mf = 0; mf < 2; mf++) {
                int s0 = mf * 2, s1 = mf * 2 + 1;
                sacc[s0] = fmaf(h[s0][0], fabsf(yv[s0].x - c[mf][0]), sacc[s0]);
                sacc[s0] = fmaf(h[s0][1], fabsf(yv[s0].y - c[mf][1]), sacc[s0]);
                sacc[s1] = fmaf(h[s1][0], fabsf(yv[s1].x - c[mf][2]), sacc[s1]);
                sacc[s1] = fmaf(h[s1][1], fabsf(yv[s1].y - c[mf][3]), sacc[s1]);
            }
        }

        // reduce over the quad (warp's 8 cols), then across 8 warps via smem
#pragma unroll
        for (int s = 0; s < 4; s++) {
            sacc[s] += __shfl_xor_sync(0xffffffffu, sacc[s], 1);
            sacc[s] += __shfl_xor_sync(0xffffffffu, sacc[s], 2);
        }
        if ((lane & 3) == 0) {
#pragma unroll
            for (int s = 0; s < 4; s++) {
                int rl = (s >> 1) * 16 + rq + (s & 1) * 8;
                red[rl * 8 + warp] = sacc[s];
            }
        }
        __syncthreads();
        if (tid < 32) {
            float acc = bv2v;
#pragma unroll
            for (int w = 0; w < 8; w++) acc += red[tid * 8 + w];
            g_q1[(size_t)(bt0 + tid) * N_AG + ag] = acc;
        }
    }
}

// ---------------------------------------------------------------------------
// K3: per-row epilogue (unchanged; same g_Y as K2 -> wc errors cancel)
// ---------------------------------------------------------------------------
__global__ void final_kernel(const float* __restrict__ qs,
                             const float* __restrict__ Wv2,
                             const float* __restrict__ bv2,
                             float* __restrict__ out) {
    __shared__ float absY[2048];
    __shared__ float qs2[32];
    __shared__ float red[4];

    const int b = blockIdx.x;
    const int e = threadIdx.x;
    const int lane = e & 31, warp = e >> 5;
    const float* Yr = g_Y + (size_t)b * NP;

    float h = 0.f;
#pragma unroll
    for (int a = 0; a < 32; a++) {
        float v = fabsf(Yr[a * 64 + e]);
        absY[a * 64 + e] = v;
        h = fmaf(qs[(size_t)b * N_AG + a], v, h);
    }
    float wf = fabsf(Yr[2048 + e]);
    float b1 = Yr[2112 + e];
    float rv = fmaxf(Yr[2176 + e], 0.f) * Wv2[e];

    float t = h + b1;
    float hid = t > 0.f ? t : expm1f(t);
    float s = hid * wf;
    float sv = rv;
#pragma unroll
    for (int off = 16; off >= 1; off >>= 1) {
        s  += __shfl_xor_sync(0xffffffffu, s, off);
        sv += __shfl_xor_sync(0xffffffffu, sv, off);
    }
    if (lane == 0) { red[warp] = s; red[2 + warp] = sv; }
    __syncthreads();

    float vtot  = red[2] + red[3] + bv2[0];
    float q_tot = red[0] + red[1] + vtot;

    if (e < 32) {
        float d = fabsf(q_tot - g_q1[(size_t)b * N_AG + e]);
        float d2 = d * d;
#pragma unroll
        for (int off = 16; off >= 1; off >>= 1)
            d2 += __shfl_xor_sync(0xffffffffu, d2, off);
        float nrm = fmaxf(sqrtf(d2), 1e-12f);
        qs2[e] = qs[(size_t)b * N_AG + e] * (d / nrm);
    }
    __syncthreads();

    float h2 = 0.f;
#pragma unroll
    for (int a = 0; a < 32; a++)
        h2 = fmaf(qs2[a], absY[a * 64 + e], h2);
    float t2 = h2 + b1;
    float hid2 = t2 > 0.f ? t2 : expm1f(t2);
    float s2 = hid2 * wf;
#pragma unroll
    for (int off = 16; off >= 1; off >>= 1)
        s2 += __shfl_xor_sync(0xffffffffu, s2, off);
    if (lane == 0) red[warp] = s2;
    __syncthreads();
    if (e == 0) out[b] = red[0] + red[1] + vtot;
}

// ---------------------------------------------------------------------------
extern "C" void kernel_launch(void* const* d_in, const int* in_sizes, int n_in,
                              void* d_out, int out_size) {
    const float* agent_qs = (const float*)d_in[0];
    const float* states   = (const float*)d_in[1];
    const float* Ww1 = (const float*)d_in[2];
    const float* bw1 = (const float*)d_in[3];
    const float* Wwf = (const float*)d_in[4];
    const float* bwf = (const float*)d_in[5];
    const float* Wb1 = (const float*)d_in[6];
    const float* bb1 = (const float*)d_in[7];
    const float* Wv1 = (const float*)d_in[8];
    const float* bv1 = (const float*)d_in[9];
    const float* Wv2 = (const float*)d_in[10];
    const float* bv2 = (const float*)d_in[11];
    float* out = (float*)d_out;

    static bool attr_done = false;
    if (!attr_done) {
        cudaFuncSetAttribute(gemm_f16, cudaFuncAttributeMaxDynamicSharedMemorySize, K1_SMEM);
        cudaFuncSetAttribute(corr_mma, cudaFuncAttributeMaxDynamicSharedMemorySize, K2_SMEM);
        attr_done = true;
    }

    pack_kernel<<<512, 256>>>(states, Ww1, bw1, Wwf, bwf, Wb1, bb1, Wv1, bv1);
    gemm_f16<<<dim3(NP / 128, B_TOT / 128), 256, K1_SMEM>>>();
    corr_mma<<<K2_GRID, 256, K2_SMEM>>>(agent_qs, Wv2, bv2);
    final_kernel<<<B_TOT, 64>>>(agent_qs, Wv2, bv2, out);
}

// round 15
// speedup vs baseline: 1.2019x; 1.2019x over previous
#include <cuda_runtime.h>
#include <cuda_fp16.h>
#include <math.h>
#include <stdint.h>

#define B_TOT 2048   // 64 * 32 rows
#define S_DIM 2048
#define N_AG  32
#define EMB   64
#define NP    2304   // padded concatenated output cols (2240 -> 18*128)

// Scratch (device globals: no allocation allowed in kernel_launch)
__device__ __half g_Wh[S_DIM * NP];    // Wcat fp16 [K][N]
__device__ __half g_Sh[B_TOT * S_DIM]; // st fp16
__device__ float g_bcat[NP];
__device__ float g_Y[B_TOT * NP];      // fp16-mma st @ Wcat + bcat (fp32 accum)
__device__ float g_q1[B_TOT * N_AG];   // masked-mix outputs

// ---------------------------------------------------------------------------
// helpers
// ---------------------------------------------------------------------------
__device__ __forceinline__ void ldsm_x4(uint32_t* r, const void* p) {
    uint32_t a = (uint32_t)__cvta_generic_to_shared(p);
    asm volatile("ldmatrix.sync.aligned.m8n8.x4.shared.b16 {%0,%1,%2,%3}, [%4];"
                 : "=r"(r[0]), "=r"(r[1]), "=r"(r[2]), "=r"(r[3]) : "r"(a));
}
__device__ __forceinline__ void ldsm_x4t(uint32_t* r, const void* p) {
    uint32_t a = (uint32_t)__cvta_generic_to_shared(p);
    asm volatile("ldmatrix.sync.aligned.m8n8.x4.trans.shared.b16 {%0,%1,%2,%3}, [%4];"
                 : "=r"(r[0]), "=r"(r[1]), "=r"(r[2]), "=r"(r[3]) : "r"(a));
}
__device__ __forceinline__ void ldsm_x2t(uint32_t* r, const void* p) {
    uint32_t a = (uint32_t)__cvta_generic_to_shared(p);
    asm volatile("ldmatrix.sync.aligned.m8n8.x2.trans.shared.b16 {%0,%1}, [%2];"
                 : "=r"(r[0]), "=r"(r[1]) : "r"(a));
}
__device__ __forceinline__ void mma_fp16(float* d, const uint32_t* a, const uint32_t* b) {
    asm volatile(
        "mma.sync.aligned.m16n8k16.row.col.f32.f16.f16.f32 "
        "{%0,%1,%2,%3},{%4,%5,%6,%7},{%8,%9},{%0,%1,%2,%3};"
        : "+f"(d[0]), "+f"(d[1]), "+f"(d[2]), "+f"(d[3])
        : "r"(a[0]), "r"(a[1]), "r"(a[2]), "r"(a[3]), "r"(b[0]), "r"(b[1]));
}
__device__ __forceinline__ void cp16(uint32_t dst, const void* src) {
    asm volatile("cp.async.cg.shared.global [%0], [%1], 16;" :: "r"(dst), "l"(src));
}
#define CP_COMMIT()  asm volatile("cp.async.commit_group;" ::: "memory")
#define CP_WAIT(n)   asm volatile("cp.async.wait_group %0;" :: "n"(n) : "memory")

// ---------------------------------------------------------------------------
// Pack (vectorized): concat weights -> fp16, st -> fp16, bias.
// ---------------------------------------------------------------------------
__global__ void pack_kernel(const float* __restrict__ st,
                            const float* __restrict__ Ww1, const float* __restrict__ bw1,
                            const float* __restrict__ Wwf, const float* __restrict__ bwf,
                            const float* __restrict__ Wb1, const float* __restrict__ bb1,
                            const float* __restrict__ Wv1, const float* __restrict__ bv1) {
    const int idx = blockIdx.x * blockDim.x + threadIdx.x;
    const int stride = gridDim.x * blockDim.x;

    if (idx < NP) {
        int n = idx;
        float bv;
        if (n < 2048)      bv = bw1[n];
        else if (n < 2112) bv = bwf[n - 2048];
        else if (n < 2176) bv = bb1[n - 2112];
        else if (n < 2240) bv = bv1[n - 2176];
        else               bv = 0.f;
        g_bcat[n] = bv;
    }

    const int WQ = S_DIM * (NP / 4);
    for (int i = idx; i < WQ; i += stride) {
        int k = i / 576;
        int n = (i - k * 576) * 4;
        float4 v;
        if (n < 2048)      v = *(const float4*)(Ww1 + (size_t)k * 2048 + n);
        else if (n < 2112) v = *(const float4*)(Wwf + (size_t)k * 64 + (n - 2048));
        else if (n < 2176) v = *(const float4*)(Wb1 + (size_t)k * 64 + (n - 2112));
        else if (n < 2240) v = *(const float4*)(Wv1 + (size_t)k * 64 + (n - 2176));
        else               v = make_float4(0.f, 0.f, 0.f, 0.f);
        __half2* ph = (__half2*)(g_Wh + (size_t)i * 4);
        ph[0] = __floats2half2_rn(v.x, v.y);
        ph[1] = __floats2half2_rn(v.z, v.w);
    }

    const int SQ = B_TOT * (S_DIM / 4);
    for (int i = idx; i < SQ; i += stride) {
        float4 v = *(const float4*)(st + (size_t)i * 4);
        __half2* ph = (__half2*)(g_Sh + (size_t)i * 4);
        ph[0] = __floats2half2_rn(v.x, v.y);
        ph[1] = __floats2half2_rn(v.z, v.w);
    }
}

// ---------------------------------------------------------------------------
// K1: Y = fp16(st) @ fp16(Wcat) + bcat, single fp16 MMA, fp32 accum.
// Block 128x128, 8 warps (4m x 2n), K-chunk 64, cp.async double buffer.
// ---------------------------------------------------------------------------
#define K1_OFF_A  0
#define K1_OFF_B  18432
#define K1_BUF    35840
#define K1_SMEM   (2 * K1_BUF)

__global__ __launch_bounds__(256, 1) void gemm_f16() {
    extern __shared__ char smem[];
    const uint32_t sbase = (uint32_t)__cvta_generic_to_shared(smem);

    const int bn = blockIdx.x * 128;
    const int bm = blockIdx.y * 128;
    const int tid = threadIdx.x;
    const int lane = tid & 31;
    const int warp = tid >> 5;
    const int wm = warp & 3;
    const int wn = warp >> 2;

    const int ra  = tid >> 3,  ca = tid & 7;
    const int rb  = tid >> 4,  cb = tid & 15;

    auto issue = [&](int c, int bufi) {
        const int k0 = c * 64;
        const uint32_t bb = sbase + bufi * K1_BUF;
#pragma unroll
        for (int l = 0; l < 4; l++) {
            int r = ra + l * 32;
            cp16(bb + K1_OFF_A + (uint32_t)r * 144 + ca * 16,
                 g_Sh + (size_t)(bm + r) * S_DIM + k0 + ca * 8);
            int rr = rb + l * 16;
            cp16(bb + K1_OFF_B + (uint32_t)rr * 272 + cb * 16,
                 g_Wh + (size_t)(k0 + rr) * NP + bn + cb * 8);
        }
    };

    float d1[2][8][4];
#pragma unroll
    for (int i = 0; i < 2; i++)
#pragma unroll
        for (int j = 0; j < 8; j++)
#pragma unroll
            for (int c = 0; c < 4; c++) d1[i][j][c] = 0.f;

    issue(0, 0);
    CP_COMMIT();

    for (int c = 0; c < 32; c++) {
        const int bufi = c & 1;
        char* base = smem + bufi * K1_BUF;
        __half* Ah = (__half*)(base + K1_OFF_A);
        __half* Bh = (__half*)(base + K1_OFF_B);

        if (c < 31) {
            issue(c + 1, bufi ^ 1);
            CP_COMMIT();
            CP_WAIT(1);
        } else {
            CP_WAIT(0);
        }
        __syncthreads();

#pragma unroll
        for (int ks = 0; ks < 4; ks++) {
            uint32_t ah[2][4];
#pragma unroll
            for (int mf = 0; mf < 2; mf++) {
                const int ro = (wm * 32 + mf * 16 + (lane & 15)) * 72 + ks * 16 + (lane >> 4) * 8;
                ldsm_x4(ah[mf], &Ah[ro]);
            }
            uint32_t bh[8][2];
#pragma unroll
            for (int nq = 0; nq < 4; nq++) {
                const int bo = (ks * 16 + (lane & 15)) * 136 + wn * 64 + nq * 16 + (lane >> 4) * 8;
                uint32_t t[4];
                ldsm_x4t(t, &Bh[bo]);
                bh[nq * 2][0] = t[0]; bh[nq * 2][1] = t[1];
                bh[nq * 2 + 1][0] = t[2]; bh[nq * 2 + 1][1] = t[3];
            }
#pragma unroll
            for (int mf = 0; mf < 2; mf++)
#pragma unroll
                for (int nf = 0; nf < 8; nf++)
                    mma_fp16(d1[mf][nf], ah[mf], bh[nf]);
        }
        __syncthreads();
    }

    // epilogue: Y = d1 + bias
#pragma unroll
    for (int mf = 0; mf < 2; mf++) {
        int r0 = bm + wm * 32 + mf * 16 + (lane >> 2);
#pragma unroll
        for (int nf = 0; nf < 8; nf++) {
            int c = bn + wn * 64 + nf * 8 + (lane & 3) * 2;
            float2 bc = *(const float2*)&g_bcat[c];
            float2 o0 = { d1[mf][nf][0] + bc.x, d1[mf][nf][1] + bc.y };
            float2 o1 = { d1[mf][nf][2] + bc.x, d1[mf][nf][3] + bc.y };
            *(float2*)(g_Y + (size_t)r0 * NP + c) = o0;
            *(float2*)(g_Y + (size_t)(r0 + 8) * NP + c) = o1;
        }
    }
}

// ---------------------------------------------------------------------------
// K2 (round-13 version, restored): persistent, 64-row items, hoisted A frags,
// Y register prefetch. Item = (64-row tile, agent): 1024 items.
// ---------------------------------------------------------------------------
#define K2_GRID    296
#define K2_ITEMS   1024
#define K2_OFF_W   9216
#define K2_WBUF    9216
#define K2_OFF_QS  27648
#define K2_OFF_RED 36096
#define K2_SMEM    37120
__global__ __launch_bounds__(256, 2) void corr_mma(const float* __restrict__ qs,
                                                   const float* __restrict__ Wv2,
                                                   const float* __restrict__ bv2) {
    extern __shared__ char smem[];
    const uint32_t sbase = (uint32_t)__cvta_generic_to_shared(smem);
    __half* Sf  = (__half*)smem;                    // [64][72]
    __half* Wgf = (__half*)(smem + K2_OFF_W);       // [2][64][72]
    float* qs_s = (float*)(smem + K2_OFF_QS);       // [64][33]
    float* red  = (float*)(smem + K2_OFF_RED);      // [64][4]

    const int tid = threadIdx.x;
    const int lane = tid & 31;
    const int warp = tid >> 5;
    const int wm = warp & 1;        // 2 m-groups of 32 rows
    const int wn = warp >> 1;       // 4 n-groups of 16 cols
    const int wr = tid >> 3, wc8 = tid & 7;
    const int rloc0 = wm * 32 + (lane >> 2);
    const float bv2v = bv2[0];

    for (int item = blockIdx.x; item < K2_ITEMS; item += K2_GRID) {
        const int bt0 = (item & 31) * 64;
        const int ag  = item >> 5;
        const int yr0 = bt0 + rloc0;

        __syncthreads();   // previous item fully done before restaging

        // stage st chunk (64 x 64 fp16) + qs tile (64 x 32)
#pragma unroll
        for (int l = 0; l < 2; l++) {
            int idx = l * 256 + tid;
            int r = idx >> 3, c8 = idx & 7;
            *(uint4*)&Sf[r * 72 + c8 * 8] =
                *(const uint4*)(g_Sh + (size_t)(bt0 + r) * S_DIM + ag * 64 + c8 * 8);
        }
#pragma unroll
        for (int l = 0; l < 8; l++) {
            int idx = l * 256 + tid;
            int r = idx >> 5, c = idx & 31;
            qs_s[r * 33 + c] = qs[(size_t)(bt0 + r) * N_AG + c];
        }

        auto issueW = [&](int g, int b) {
#pragma unroll
            for (int l = 0; l < 2; l++) {
                int r = wr + l * 32;
                cp16(sbase + K2_OFF_W + b * K2_WBUF + (uint32_t)r * 144 + wc8 * 16,
                     g_Wh + (size_t)(ag * 64 + r) * NP + g * 64 + wc8 * 8);
            }
        };

        issueW(0, 0);
        CP_COMMIT();
        __syncthreads();   // Sf staged

        // hoist A fragments: invariant across all 35 groups
        uint32_t ah[2][4][4];
#pragma unroll
        for (int mf = 0; mf < 2; mf++)
#pragma unroll
            for (int ks = 0; ks < 4; ks++) {
                const int ro = (wm * 32 + mf * 16 + (lane & 15)) * 72 + ks * 16 + (lane >> 4) * 8;
                ldsm_x4(ah[mf][ks], &Sf[ro]);
            }

        auto loadY = [&](int g, float2 (&yv)[2][2][2]) {
#pragma unroll
            for (int mf = 0; mf < 2; mf++) {
                int r0 = yr0 + mf * 16;
#pragma unroll
                for (int nf = 0; nf < 2; nf++) {
                    int col = g * 64 + wn * 16 + nf * 8 + (lane & 3) * 2;
                    yv[mf][nf][0] = *(const float2*)(g_Y + (size_t)r0 * NP + col);
                    yv[mf][nf][1] = *(const float2*)(g_Y + (size_t)(r0 + 8) * NP + col);
                }
            }
        };

        auto computeC = [&](const __half* WgfB, float (&c)[2][2][4]) {
#pragma unroll
            for (int mf = 0; mf < 2; mf++)
#pragma unroll
                for (int nf = 0; nf < 2; nf++)
#pragma unroll
                    for (int q = 0; q < 4; q++) c[mf][nf][q] = 0.f;
#pragma unroll
            for (int ks = 0; ks < 4; ks++) {
                uint32_t t[4];
                const int bo = (ks * 16 + (lane & 15)) * 72 + wn * 16 + (lane >> 4) * 8;
                ldsm_x4t(t, &WgfB[bo]);
#pragma unroll
                for (int mf = 0; mf < 2; mf++) {
                    mma_fp16(c[mf][0], ah[mf][ks], &t[0]);
                    mma_fp16(c[mf][1], ah[mf][ks], &t[2]);
                }
            }
        };

        float h[4][4];
#pragma unroll
        for (int s = 0; s < 4; s++)
#pragma unroll
            for (int e = 0; e < 4; e++) h[s][e] = 0.f;
        float vp[4] = {0.f, 0.f, 0.f, 0.f};

        // ---- hot loop: w1 groups 0..31 ----
        for (int g = 0; g < 32; g++) {
            CP_WAIT(0);
            __syncthreads();
            issueW(g == 31 ? 33 : g + 1, (g + 1) & 1);
            CP_COMMIT();

            float2 yv[2][2][2];
            loadY(g, yv);
            float qv[4];
#pragma unroll
            for (int s = 0; s < 4; s++) {
                int rl = rloc0 + (s >> 1) * 16 + (s & 1) * 8;
                qv[s] = qs_s[rl * 33 + g];
            }

            float c[2][2][4];
            computeC(Wgf + (g & 1) * 4608, c);

#pragma unroll
            for (int mf = 0; mf < 2; mf++) {
#pragma unroll
                for (int nf = 0; nf < 2; nf++) {
                    int s0 = mf * 2, s1 = mf * 2 + 1;
                    int e0 = nf * 2, e1 = nf * 2 + 1;
                    h[s0][e0] = fmaf(qv[s0], fabsf(yv[mf][nf][0].x - c[mf][nf][0]), h[s0][e0]);
                    h[s0][e1] = fmaf(qv[s0], fabsf(yv[mf][nf][0].y - c[mf][nf][1]), h[s0][e1]);
                    h[s1][e0] = fmaf(qv[s1], fabsf(yv[mf][nf][1].x - c[mf][nf][2]), h[s1][e0]);
                    h[s1][e1] = fmaf(qv[s1], fabsf(yv[mf][nf][1].y - c[mf][nf][3]), h[s1][e1]);
                }
            }
        }

        // ---- tail group 33 (b1): hidden = elu(h + m), buffer 0 ----
        CP_WAIT(0);
        __syncthreads();
        issueW(34, 1);
        CP_COMMIT();
        {
            float2 yv[2][2][2];
            loadY(33, yv);
            float c[2][2][4];
            computeC(Wgf + 0 * 4608, c);
#pragma unroll
            for (int mf = 0; mf < 2; mf++) {
#pragma unroll
                for (int nf = 0; nf < 2; nf++) {
                    int s0 = mf * 2, s1 = mf * 2 + 1;
                    int e0 = nf * 2, e1 = nf * 2 + 1;
                    float t;
                    t = h[s0][e0] + (yv[mf][nf][0].x - c[mf][nf][0]); h[s0][e0] = t > 0.f ? t : expm1f(t);
                    t = h[s0][e1] + (yv[mf][nf][0].y - c[mf][nf][1]); h[s0][e1] = t > 0.f ? t : expm1f(t);
                    t = h[s1][e0] + (yv[mf][nf][1].x - c[mf][nf][2]); h[s1][e0] = t > 0.f ? t : expm1f(t);
                    t = h[s1][e1] + (yv[mf][nf][1].y - c[mf][nf][3]); h[s1][e1] = t > 0.f ? t : expm1f(t);
                }
            }
        }

        // ---- tail group 34 (v1): vp += relu(m) * Wv2, buffer 1 ----
        CP_WAIT(0);
        __syncthreads();
        issueW(32, 0);
        CP_COMMIT();
        {
            float2 yv[2][2][2];
            loadY(34, yv);
            float c[2][2][4];
            computeC(Wgf + 1 * 4608, c);
#pragma unroll
            for (int mf = 0; mf < 2; mf++) {
#pragma unroll
                for (int nf = 0; nf < 2; nf++) {
                    int e = wn * 16 + nf * 8 + (lane & 3) * 2;
                    float w0 = Wv2[e], w1 = Wv2[e + 1];
                    int s0 = mf * 2, s1 = mf * 2 + 1;
                    vp[s0] = fmaf(fmaxf(yv[mf][nf][0].x - c[mf][nf][0], 0.f), w0, vp[s0]);
                    vp[s0] = fmaf(fmaxf(yv[mf][nf][0].y - c[mf][nf][1], 0.f), w1, vp[s0]);
                    vp[s1] = fmaf(fmaxf(yv[mf][nf][1].x - c[mf][nf][2], 0.f), w0, vp[s1]);
                    vp[s1] = fmaf(fmaxf(yv[mf][nf][1].y - c[mf][nf][3], 0.f), w1, vp[s1]);
                }
            }
        }

        // ---- tail group 32 (w_final): s = vp + sum_e hidden * |m|, buffer 0 ----
        CP_WAIT(0);
        __syncthreads();
        float sacc[4] = { vp[0], vp[1], vp[2], vp[3] };
        {
            float2 yv[2][2][2];
            loadY(32, yv);
            float c[2][2][4];
            computeC(Wgf + 0 * 4608, c);
#pragma unroll
            for (int mf = 0; mf < 2; mf++) {
#pragma unroll
                for (int nf = 0; nf < 2; nf++) {
                    int s0 = mf * 2, s1 = mf * 2 + 1;
                    int e0 = nf * 2, e1 = nf * 2 + 1;
                    sacc[s0] = fmaf(h[s0][e0], fabsf(yv[mf][nf][0].x - c[mf][nf][0]), sacc[s0]);
                    sacc[s0] = fmaf(h[s0][e1], fabsf(yv[mf][nf][0].y - c[mf][nf][1]), sacc[s0]);
                    sacc[s1] = fmaf(h[s1][e0], fabsf(yv[mf][nf][1].x - c[mf][nf][2]), sacc[s1]);
                    sacc[s1] = fmaf(h[s1][e1], fabsf(yv[mf][nf][1].y - c[mf][nf][3]), sacc[s1]);
                }
            }
        }

#pragma unroll
        for (int s = 0; s < 4; s++) {
            sacc[s] += __shfl_xor_sync(0xffffffffu, sacc[s], 1);
            sacc[s] += __shfl_xor_sync(0xffffffffu, sacc[s], 2);
        }
        if ((lane & 3) == 0) {
#pragma unroll
            for (int s = 0; s < 4; s++) {
                int rl = rloc0 + (s >> 1) * 16 + (s & 1) * 8;
                red[rl * 4 + wn] = sacc[s];
            }
        }
        __syncthreads();
        if (tid < 64)
            g_q1[(size_t)(bt0 + tid) * N_AG + ag] =
                red[tid * 4] + red[tid * 4 + 1] + red[tid * 4 + 2] + red[tid * 4 + 3] + bv2v;
    }
}

// ---------------------------------------------------------------------------
// K3: per-row epilogue, re-blocked: 4 rows per 256-thread block (same per-row
// arithmetic and order as before -> bit-identical output).
// ---------------------------------------------------------------------------
__global__ __launch_bounds__(256) void final_kernel(const float* __restrict__ qs,
                                                    const float* __restrict__ Wv2,
                                                    const float* __restrict__ bv2,
                                                    float* __restrict__ out) {
    __shared__ float absY[4][2048];
    __shared__ float qs2[4][32];
    __shared__ float red[4][4];

    const int rg = threadIdx.x >> 6;     // row group 0..3
    const int e  = threadIdx.x & 63;     // 0..63
    const int lane = e & 31, wh = e >> 5;
    const int b = blockIdx.x * 4 + rg;
    const float* Yr = g_Y + (size_t)b * NP;

    float h = 0.f;
#pragma unroll
    for (int a = 0; a < 32; a++) {
        float v = fabsf(Yr[a * 64 + e]);
        absY[rg][a * 64 + e] = v;
        h = fmaf(qs[(size_t)b * N_AG + a], v, h);
    }
    float wf = fabsf(Yr[2048 + e]);
    float b1 = Yr[2112 + e];
    float rv = fmaxf(Yr[2176 + e], 0.f) * Wv2[e];

    float t = h + b1;
    float hid = t > 0.f ? t : expm1f(t);
    float s = hid * wf;
    float sv = rv;
#pragma unroll
    for (int off = 16; off >= 1; off >>= 1) {
        s  += __shfl_xor_sync(0xffffffffu, s, off);
        sv += __shfl_xor_sync(0xffffffffu, sv, off);
    }
    if (lane == 0) { red[rg][wh] = s; red[rg][2 + wh] = sv; }
    __syncthreads();

    float vtot  = red[rg][2] + red[rg][3] + bv2[0];
    float q_tot = red[rg][0] + red[rg][1] + vtot;

    if (e < 32) {
        float d = fabsf(q_tot - g_q1[(size_t)b * N_AG + e]);
        float d2 = d * d;
#pragma unroll
        for (int off = 16; off >= 1; off >>= 1)
            d2 += __shfl_xor_sync(0xffffffffu, d2, off);
        float nrm = fmaxf(sqrtf(d2), 1e-12f);
        qs2[rg][e] = qs[(size_t)b * N_AG + e] * (d / nrm);
    }
    __syncthreads();

    float h2 = 0.f;
#pragma unroll
    for (int a = 0; a < 32; a++)
        h2 = fmaf(qs2[rg][a], absY[rg][a * 64 + e], h2);
    float t2 = h2 + b1;
    float hid2 = t2 > 0.f ? t2 : expm1f(t2);
    float s2 = hid2 * wf;
#pragma unroll
    for (int off = 16; off >= 1; off >>= 1)
        s2 += __shfl_xor_sync(0xffffffffu, s2, off);
    if (lane == 0) red[rg][wh] = s2;
    __syncthreads();
    if (e == 0) out[b] = red[rg][0] + red[rg][1] + vtot;
}

// ---------------------------------------------------------------------------
extern "C" void kernel_launch(void* const* d_in, const int* in_sizes, int n_in,
                              void* d_out, int out_size) {
    const float* agent_qs = (const float*)d_in[0];
    const float* states   = (const float*)d_in[1];
    const float* Ww1 = (const float*)d_in[2];
    const float* bw1 = (const float*)d_in[3];
    const float* Wwf = (const float*)d_in[4];
    const float* bwf = (const float*)d_in[5];
    const float* Wb1 = (const float*)d_in[6];
    const float* bb1 = (const float*)d_in[7];
    const float* Wv1 = (const float*)d_in[8];
    const float* bv1 = (const float*)d_in[9];
    const float* Wv2 = (const float*)d_in[10];
    const float* bv2 = (const float*)d_in[11];
    float* out = (float*)d_out;

    static bool attr_done = false;
    if (!attr_done) {
        cudaFuncSetAttribute(gemm_f16, cudaFuncAttributeMaxDynamicSharedMemorySize, K1_SMEM);
        cudaFuncSetAttribute(corr_mma, cudaFuncAttributeMaxDynamicSharedMemorySize, K2_SMEM);
        attr_done = true;
    }

    pack_kernel<<<1184, 256>>>(states, Ww1, bw1, Wwf, bwf, Wb1, bb1, Wv1, bv1);
    gemm_f16<<<dim3(NP / 128, B_TOT / 128), 256, K1_SMEM>>>();
    corr_mma<<<K2_GRID, 256, K2_SMEM>>>(agent_qs, Wv2, bv2);
    final_kernel<<<B_TOT / 4, 256>>>(agent_qs, Wv2, bv2, out);
}